// round 2
// baseline (speedup 1.0000x reference)
#include <cuda_runtime.h>
#include <math.h>

#define N_NODES   8192
#define HIDDEN    256
#define HEADS     4
#define HEAD_DIM  64
#define NUM_EDGES 4096
#define NUM_INC   65536
#define OUT_ELEMS (N_NODES*HIDDEN)
#define GEMM_BLOCKS 128
#define MT 64
#define KT 32

// ---------------- scratch (device globals; no allocation allowed) ----------------
__device__ float    g_v[HEADS*HIDDEN];
__device__ float    g_bh[HEADS];
__device__ float    g_nlogit[N_NODES*HEADS];   // float4 per node
__device__ int      g_ecount[NUM_EDGES];
__device__ int      g_estart[NUM_EDGES+1];
__device__ int      g_efill[NUM_EDGES];
__device__ int      g_eperm[NUM_INC];
__device__ int      g_ncount[N_NODES];
__device__ int      g_nstart[N_NODES+1];
__device__ int      g_nfill[N_NODES];
__device__ int      g_nperm[NUM_INC];
__device__ float    g_attn[NUM_INC];
__device__ float    g_nattn[N_NODES];

// ---------------- init counters ----------------
__global__ void k_init(){
    int i = blockIdx.x*blockDim.x + threadIdx.x;
    if (i < NUM_EDGES){ g_ecount[i] = 0; g_efill[i] = 0; }
    if (i < N_NODES)  { g_ncount[i] = 0; g_nfill[i] = 0; g_nattn[i] = 0.f; }
}

// ---------------- fold first GEMM: v_h = edge_att_h^T W_w_h ----------------
__global__ void k_prep(const float* __restrict__ W_w, const float* __restrict__ W_b,
                       const float* __restrict__ att){
    int k = threadIdx.x;  // 256 threads
    #pragma unroll
    for (int h = 0; h < HEADS; h++){
        float s = 0.f;
        #pragma unroll 8
        for (int d = 0; d < HEAD_DIM; d++)
            s += W_w[(h*HEAD_DIM + d)*HIDDEN + k] * att[h*HEAD_DIM + d];
        g_v[h*HIDDEN + k] = s;
    }
    if (k < HEADS){
        float s = 0.f;
        #pragma unroll 8
        for (int d = 0; d < HEAD_DIM; d++)
            s += W_b[k*HEAD_DIM + d] * att[k*HEAD_DIM + d];
        g_bh[k] = s;
    }
}

// ---------------- node logits: 8 threads/node, float4 coalesced ----------------
__global__ __launch_bounds__(256) void k_nlogit(const float* __restrict__ x){
    __shared__ float sv[HEADS*HIDDEN];
    for (int i = threadIdx.x; i < HEADS*HIDDEN; i += 256) sv[i] = g_v[i];
    __syncthreads();
    int tid = threadIdx.x;
    int c = tid & 7;              // 8 threads per node
    int n = blockIdx.x*32 + (tid >> 3);
    const float4* xr = (const float4*)(x + (long)n*HIDDEN);
    const float4* v0 = (const float4*)(sv);
    const float4* v1 = (const float4*)(sv + 256);
    const float4* v2 = (const float4*)(sv + 512);
    const float4* v3 = (const float4*)(sv + 768);
    float a0=0.f, a1=0.f, a2=0.f, a3=0.f;
    #pragma unroll
    for (int i = 0; i < 8; i++){
        int j = i*8 + c;
        float4 xv = xr[j];
        float4 w;
        w = v0[j]; a0 += xv.x*w.x + xv.y*w.y + xv.z*w.z + xv.w*w.w;
        w = v1[j]; a1 += xv.x*w.x + xv.y*w.y + xv.z*w.z + xv.w*w.w;
        w = v2[j]; a2 += xv.x*w.x + xv.y*w.y + xv.z*w.z + xv.w*w.w;
        w = v3[j]; a3 += xv.x*w.x + xv.y*w.y + xv.z*w.z + xv.w*w.w;
    }
    #pragma unroll
    for (int off = 1; off < 8; off <<= 1){
        a0 += __shfl_xor_sync(0xffffffffu, a0, off);
        a1 += __shfl_xor_sync(0xffffffffu, a1, off);
        a2 += __shfl_xor_sync(0xffffffffu, a2, off);
        a3 += __shfl_xor_sync(0xffffffffu, a3, off);
    }
    if (c == 0){
        float4 r = make_float4(a0 + g_bh[0], a1 + g_bh[1], a2 + g_bh[2], a3 + g_bh[3]);
        ((float4*)g_nlogit)[n] = r;
    }
}

// ---------------- count incidences per edge and per node ----------------
__global__ void k_count(const int* __restrict__ node_idx, const int* __restrict__ edge_idx){
    int i = blockIdx.x*blockDim.x + threadIdx.x;
    atomicAdd(&g_ecount[edge_idx[i]], 1);
    atomicAdd(&g_ncount[node_idx[i]], 1);
}

// ---------------- two prefix sums (block 0: edges, block 1: nodes) ----------------
template<int IPT, int NITEMS>
__device__ void scan_block(const int* __restrict__ cnt, int* __restrict__ start){
    __shared__ int sh[1024];
    int t = threadIdx.x;
    int loc[IPT];
    int run = 0;
    int base = t*IPT;
    #pragma unroll
    for (int k = 0; k < IPT; k++){ loc[k] = run; run += cnt[base+k]; }
    sh[t] = run;
    __syncthreads();
    #pragma unroll
    for (int off = 1; off < 1024; off <<= 1){
        int v = (t >= off) ? sh[t-off] : 0;
        __syncthreads();
        sh[t] += v;
        __syncthreads();
    }
    int prev = t ? sh[t-1] : 0;
    #pragma unroll
    for (int k = 0; k < IPT; k++) start[base+k] = prev + loc[k];
    if (t == 1023) start[NITEMS] = sh[1023];
}
__global__ void k_scan(){
    if (blockIdx.x == 0) scan_block<4, NUM_EDGES>(g_ecount, g_estart);
    else                 scan_block<8, N_NODES>(g_ncount, g_nstart);
}

// ---------------- fill both CSRs ----------------
__global__ void k_fill(const int* __restrict__ node_idx, const int* __restrict__ edge_idx){
    int i = blockIdx.x*blockDim.x + threadIdx.x;
    int e = edge_idx[i], n = node_idx[i];
    int pe = atomicAdd(&g_efill[e], 1);
    g_eperm[g_estart[e] + pe] = i;
    int pn = atomicAdd(&g_nfill[n], 1);
    g_nperm[g_nstart[n] + pn] = i;
}

// ---------------- per-edge softmax (warp per edge) + per-node attn sums ----------------
__global__ __launch_bounds__(256) void k_edge(const int* __restrict__ node_idx){
    int gw = (blockIdx.x*blockDim.x + threadIdx.x) >> 5;
    int lane = threadIdx.x & 31;
    if (gw >= NUM_EDGES) return;
    int s = g_estart[gw], cnt = g_ecount[gw];
    if (cnt == 0) return;
    const float4* NL = (const float4*)g_nlogit;

    float m0=-1e30f, m1=-1e30f, m2=-1e30f, m3=-1e30f;
    for (int t = lane; t < cnt; t += 32){
        int n = node_idx[g_eperm[s+t]];
        float4 l = NL[n];
        m0 = fmaxf(m0, l.x); m1 = fmaxf(m1, l.y);
        m2 = fmaxf(m2, l.z); m3 = fmaxf(m3, l.w);
    }
    #pragma unroll
    for (int off = 16; off; off >>= 1){
        m0 = fmaxf(m0, __shfl_xor_sync(0xffffffffu, m0, off));
        m1 = fmaxf(m1, __shfl_xor_sync(0xffffffffu, m1, off));
        m2 = fmaxf(m2, __shfl_xor_sync(0xffffffffu, m2, off));
        m3 = fmaxf(m3, __shfl_xor_sync(0xffffffffu, m3, off));
    }
    float s0=0.f, s1=0.f, s2=0.f, s3=0.f;
    for (int t = lane; t < cnt; t += 32){
        int n = node_idx[g_eperm[s+t]];
        float4 l = NL[n];
        s0 += expf(l.x - m0); s1 += expf(l.y - m1);
        s2 += expf(l.z - m2); s3 += expf(l.w - m3);
    }
    #pragma unroll
    for (int off = 16; off; off >>= 1){
        s0 += __shfl_xor_sync(0xffffffffu, s0, off);
        s1 += __shfl_xor_sync(0xffffffffu, s1, off);
        s2 += __shfl_xor_sync(0xffffffffu, s2, off);
        s3 += __shfl_xor_sync(0xffffffffu, s3, off);
    }
    bool valid = (cnt >= 2);
    float r0 = 1.f/s0, r1 = 1.f/s1, r2 = 1.f/s2, r3 = 1.f/s3;
    for (int t = lane; t < cnt; t += 32){
        int inc = g_eperm[s+t];
        int n = node_idx[inc];
        float a = 0.f;
        if (valid){
            float4 l = NL[n];
            a = 0.25f*(expf(l.x - m0)*r0 + expf(l.y - m1)*r1 +
                       expf(l.z - m2)*r2 + expf(l.w - m3)*r3);
        }
        g_attn[inc] = a;
        atomicAdd(&g_nattn[n], a);
    }
}

// ---------------- fused final: GEMM+LN (blocks 0..127) || AW row writer (rest) ----------------
__global__ __launch_bounds__(256) void k_final(const float* __restrict__ x,
                                               const float* __restrict__ out_w,
                                               const float* __restrict__ out_b,
                                               const int* __restrict__ node_idx,
                                               const int* __restrict__ edge_idx,
                                               float* __restrict__ out,
                                               float* __restrict__ AW){
    extern __shared__ float smf[];
    int tid = threadIdx.x;

    if (blockIdx.x < GEMM_BLOCKS){
        // ---- y = (x*scale) @ out_w^T + out_b, then LayerNorm ----
        float (*As)[MT+1]     = (float(*)[MT+1])smf;                    // 32 x 65
        float (*Bs)[HIDDEN+1] = (float(*)[HIDDEN+1])(smf + KT*(MT+1));  // 32 x 257
        float* Ss             = smf + KT*(MT+1) + KT*(HIDDEN+1);        // 64
        int tx = tid & 15;
        int ty = tid >> 4;
        int row0 = blockIdx.x * MT;

        if (tid < MT){
            int rr = row0 + tid;
            float c = (float)g_ncount[rr];
            Ss[tid] = g_nattn[rr] / fmaxf(c, 1.0f);
        }
        __syncthreads();

        float acc[4][16];
        #pragma unroll
        for (int i = 0; i < 4; i++)
            #pragma unroll
            for (int j = 0; j < 16; j++) acc[i][j] = 0.f;

        for (int k0 = 0; k0 < HIDDEN; k0 += KT){
            #pragma unroll
            for (int r = 0; r < 8; r++){
                int q = tid + 256*r;
                int m = q >> 5, k = q & 31;
                As[k][m] = x[(long)(row0+m)*HIDDEN + k0 + k] * Ss[m];
            }
            #pragma unroll
            for (int r = 0; r < 32; r++){
                int q = tid + 256*r;
                int j = q >> 5, k = q & 31;
                Bs[k][j] = out_w[(long)j*HIDDEN + k0 + k];
            }
            __syncthreads();
            #pragma unroll
            for (int k = 0; k < KT; k++){
                float a[4], b[16];
                #pragma unroll
                for (int i = 0; i < 4; i++) a[i] = As[k][ty*4 + i];
                #pragma unroll
                for (int j = 0; j < 16; j++) b[j] = Bs[k][tx + 16*j];
                #pragma unroll
                for (int i = 0; i < 4; i++)
                    #pragma unroll
                    for (int j = 0; j < 16; j++) acc[i][j] += a[i]*b[j];
            }
            __syncthreads();
        }

        #pragma unroll
        for (int j = 0; j < 16; j++){
            float bb = out_b[tx + 16*j];
            #pragma unroll
            for (int i = 0; i < 4; i++) acc[i][j] += bb;
        }

        #pragma unroll
        for (int i = 0; i < 4; i++){
            float s = 0.f, s2 = 0.f;
            #pragma unroll
            for (int j = 0; j < 16; j++){ s += acc[i][j]; s2 += acc[i][j]*acc[i][j]; }
            #pragma unroll
            for (int off = 8; off; off >>= 1){
                s  += __shfl_xor_sync(0xffffffffu, s,  off);
                s2 += __shfl_xor_sync(0xffffffffu, s2, off);
            }
            float mu  = s * (1.f/256.f);
            float var = s2 * (1.f/256.f) - mu*mu;
            float inv = rsqrtf(var + 1e-5f);
            int row = row0 + ty*4 + i;
            float* op = out + (long)row*HIDDEN;
            #pragma unroll
            for (int j = 0; j < 16; j++)
                op[tx + 16*j] = (acc[i][j] - mu) * inv;
        }
    } else {
        // ---- one dense AW row per block: smem accumulate then stream write ----
        float* srow = smf;                   // 8192 floats
        float4* srow4 = (float4*)srow;
        float4 z4 = make_float4(0.f,0.f,0.f,0.f);
        #pragma unroll
        for (int i = 0; i < 8; i++) srow4[tid + 256*i] = z4;
        __syncthreads();

        int n = blockIdx.x - GEMM_BLOCKS;
        int s = g_nstart[n], dcnt = g_ncount[n];
        int warp = tid >> 5, lane = tid & 31;
        for (int q = warp; q < dcnt; q += 8){
            int inc = g_nperm[s + q];
            float a = g_attn[inc];
            if (a != 0.f){
                int e = edge_idx[inc];
                int es = g_estart[e], ec = g_ecount[e];
                for (int t = lane; t < ec; t += 32){
                    int col = node_idx[g_eperm[es + t]];
                    atomicAdd(&srow[col], a);
                }
            }
        }
        __syncthreads();
        if (tid == 0) srow[n] = 0.f;       // diagonal zeroed
        __syncthreads();
        float4* dst = (float4*)(AW + (long)n*N_NODES);
        #pragma unroll
        for (int i = 0; i < 8; i++) dst[tid + 256*i] = srow4[tid + 256*i];
    }
}

// ---------------- launch ----------------
extern "C" void kernel_launch(void* const* d_in, const int* in_sizes, int n_in,
                              void* d_out, int out_size){
    const float* x        = (const float*)d_in[0];
    const int*   node_idx = (const int*)  d_in[1];
    const int*   edge_idx = (const int*)  d_in[2];
    const float* W_w      = (const float*)d_in[3];
    const float* W_b      = (const float*)d_in[4];
    const float* att      = (const float*)d_in[5];
    const float* out_w    = (const float*)d_in[6];
    const float* out_b    = (const float*)d_in[7];
    float* out = (float*)d_out;
    float* AW  = out + OUT_ELEMS;

    const int gemm_smem = (KT*(MT+1) + KT*(HIDDEN+1) + MT) * sizeof(float); // 41472
    k_init  <<<32, 256>>>();
    k_prep  <<<1, 256>>>(W_w, W_b, att);
    k_nlogit<<<N_NODES/32, 256>>>(x);
    k_count <<<NUM_INC/256, 256>>>(node_idx, edge_idx);
    k_scan  <<<2, 1024>>>();
    k_fill  <<<NUM_INC/256, 256>>>(node_idx, edge_idx);
    k_edge  <<<NUM_EDGES/8, 256>>>(node_idx);
    k_final <<<GEMM_BLOCKS + N_NODES, 256, gemm_smem>>>(x, out_w, out_b,
                                                        node_idx, edge_idx, out, AW);
}

// round 4
// speedup vs baseline: 1.2551x; 1.2551x over previous
#include <cuda_runtime.h>
#include <math.h>

#define N_NODES   8192
#define HIDDEN    256
#define HEADS     4
#define HEAD_DIM  64
#define NUM_EDGES 4096
#define NUM_INC   65536
#define OUT_ELEMS (N_NODES*HIDDEN)
#define GEMM_BLOCKS 128
#define MT 64
#define KT 16

// ---------------- scratch (device globals) ----------------
__device__ float    g_v[HEADS*HIDDEN];
__device__ float    g_bh[HEADS];
__device__ float    g_nlogit[N_NODES*HEADS];   // float4 per node
__device__ int      g_ecount[NUM_EDGES];
__device__ int      g_estart[NUM_EDGES+1];
__device__ int      g_efill[NUM_EDGES];
__device__ int      g_ncount[N_NODES];
__device__ int      g_nstart[N_NODES+1];
__device__ int      g_nfill[N_NODES];
__device__ int      g_ecols[NUM_INC];   // edge-CSR: member node ids
__device__ int      g_enpos[NUM_INC];   // edge-CSR: node-CSR position of that incidence
__device__ int      g_nedge[NUM_INC];   // node-CSR: edge id of incidence
__device__ float    g_attn_np[NUM_INC]; // attn per incidence, node-CSR order
__device__ float    g_nattn[N_NODES];

// ================= K1: prep (b0) + zero-init (b1..32) — disjoint writes ============
__global__ __launch_bounds__(256) void k1(const float* __restrict__ W_w,
                                          const float* __restrict__ W_b,
                                          const float* __restrict__ att){
    int b = blockIdx.x, tid = threadIdx.x;
    if (b == 0){
        int k = tid;
        #pragma unroll
        for (int h = 0; h < HEADS; h++){
            float s = 0.f;
            #pragma unroll 8
            for (int d = 0; d < HEAD_DIM; d++)
                s += W_w[(h*HEAD_DIM + d)*HIDDEN + k] * att[h*HEAD_DIM + d];
            g_v[h*HIDDEN + k] = s;
        }
        if (k < HEADS){
            float s = 0.f;
            #pragma unroll 8
            for (int d = 0; d < HEAD_DIM; d++)
                s += W_b[k*HEAD_DIM + d] * att[k*HEAD_DIM + d];
            g_bh[k] = s;
        }
    } else {
        int i = (b-1)*256 + tid;
        g_ncount[i] = 0; g_nfill[i] = 0; g_nattn[i] = 0.f;
        if (i < NUM_EDGES){ g_ecount[i] = 0; g_efill[i] = 0; }
    }
}

// ================= K2: count (b0..63) + nlogit (b64..319) — no write conflicts =====
__global__ __launch_bounds__(256) void k2(const float* __restrict__ x,
                                          const int* __restrict__ node_idx,
                                          const int* __restrict__ edge_idx){
    int b = blockIdx.x, tid = threadIdx.x;
    if (b < 64){
        int i = b*256 + tid;
        int4 ni = ((const int4*)node_idx)[i];
        int4 ei = ((const int4*)edge_idx)[i];
        atomicAdd(&g_ecount[ei.x], 1); atomicAdd(&g_ecount[ei.y], 1);
        atomicAdd(&g_ecount[ei.z], 1); atomicAdd(&g_ecount[ei.w], 1);
        atomicAdd(&g_ncount[ni.x], 1); atomicAdd(&g_ncount[ni.y], 1);
        atomicAdd(&g_ncount[ni.z], 1); atomicAdd(&g_ncount[ni.w], 1);
    } else {
        __shared__ float sv[HEADS*HIDDEN];
        for (int i = tid; i < HEADS*HIDDEN; i += 256) sv[i] = g_v[i];
        __syncthreads();
        int c = tid & 7;
        int n = (b-64)*32 + (tid >> 3);
        const float4* xr = (const float4*)(x + (long)n*HIDDEN);
        const float4* v0 = (const float4*)(sv);
        const float4* v1 = (const float4*)(sv + 256);
        const float4* v2 = (const float4*)(sv + 512);
        const float4* v3 = (const float4*)(sv + 768);
        float a0=0.f, a1=0.f, a2=0.f, a3=0.f;
        #pragma unroll
        for (int i = 0; i < 8; i++){
            int j = i*8 + c;
            float4 xv = xr[j];
            float4 w;
            w = v0[j]; a0 += xv.x*w.x + xv.y*w.y + xv.z*w.z + xv.w*w.w;
            w = v1[j]; a1 += xv.x*w.x + xv.y*w.y + xv.z*w.z + xv.w*w.w;
            w = v2[j]; a2 += xv.x*w.x + xv.y*w.y + xv.z*w.z + xv.w*w.w;
            w = v3[j]; a3 += xv.x*w.x + xv.y*w.y + xv.z*w.z + xv.w*w.w;
        }
        #pragma unroll
        for (int off = 1; off < 8; off <<= 1){
            a0 += __shfl_xor_sync(0xffffffffu, a0, off);
            a1 += __shfl_xor_sync(0xffffffffu, a1, off);
            a2 += __shfl_xor_sync(0xffffffffu, a2, off);
            a3 += __shfl_xor_sync(0xffffffffu, a3, off);
        }
        if (c == 0){
            float4 r = make_float4(a0 + g_bh[0], a1 + g_bh[1], a2 + g_bh[2], a3 + g_bh[3]);
            ((float4*)g_nlogit)[n] = r;
        }
    }
}

// ================= K3: two prefix scans =============================================
template<int IPT, int NITEMS>
__device__ void scan_block(const int* __restrict__ cnt, int* __restrict__ start){
    __shared__ int sh[1024];
    int t = threadIdx.x;
    int loc[IPT];
    int run = 0;
    int base = t*IPT;
    #pragma unroll
    for (int k = 0; k < IPT; k++){ loc[k] = run; run += cnt[base+k]; }
    sh[t] = run;
    __syncthreads();
    for (int off = 1; off < 1024; off <<= 1){
        int v = (t >= off) ? sh[t-off] : 0;
        __syncthreads();
        sh[t] += v;
        __syncthreads();
    }
    int prev = t ? sh[t-1] : 0;
    #pragma unroll
    for (int k = 0; k < IPT; k++) start[base+k] = prev + loc[k];
    if (t == 1023) start[NITEMS] = sh[1023];
}
__global__ __launch_bounds__(1024) void k3(){
    if (blockIdx.x == 0) scan_block<4, NUM_EDGES>(g_ecount, g_estart);
    else                 scan_block<8, N_NODES>(g_ncount, g_nstart);
}

// ================= K4: fill both CSRs with flat payloads ===========================
__global__ __launch_bounds__(256) void k4(const int* __restrict__ node_idx,
                                          const int* __restrict__ edge_idx){
    int i = blockIdx.x*256 + threadIdx.x;
    int e = edge_idx[i], n = node_idx[i];
    int pe = atomicAdd(&g_efill[e], 1);
    int pn = atomicAdd(&g_nfill[n], 1);
    int epos = g_estart[e] + pe;
    int npos = g_nstart[n] + pn;
    g_ecols[epos] = n;
    g_enpos[epos] = npos;
    g_nedge[npos] = e;
}

// ================= K5: per-edge softmax (warp per edge) ============================
__global__ __launch_bounds__(256) void k5(){
    int gw = (blockIdx.x*256 + threadIdx.x) >> 5;
    int lane = threadIdx.x & 31;
    int s = g_estart[gw], cnt = g_ecount[gw];
    if (cnt == 0) return;
    const float4* NL = (const float4*)g_nlogit;

    float m0=-1e30f, m1=-1e30f, m2=-1e30f, m3=-1e30f;
    for (int t = lane; t < cnt; t += 32){
        float4 l = NL[g_ecols[s+t]];
        m0 = fmaxf(m0, l.x); m1 = fmaxf(m1, l.y);
        m2 = fmaxf(m2, l.z); m3 = fmaxf(m3, l.w);
    }
    #pragma unroll
    for (int off = 16; off; off >>= 1){
        m0 = fmaxf(m0, __shfl_xor_sync(0xffffffffu, m0, off));
        m1 = fmaxf(m1, __shfl_xor_sync(0xffffffffu, m1, off));
        m2 = fmaxf(m2, __shfl_xor_sync(0xffffffffu, m2, off));
        m3 = fmaxf(m3, __shfl_xor_sync(0xffffffffu, m3, off));
    }
    float s0=0.f, s1=0.f, s2=0.f, s3=0.f;
    for (int t = lane; t < cnt; t += 32){
        float4 l = NL[g_ecols[s+t]];
        s0 += expf(l.x - m0); s1 += expf(l.y - m1);
        s2 += expf(l.z - m2); s3 += expf(l.w - m3);
    }
    #pragma unroll
    for (int off = 16; off; off >>= 1){
        s0 += __shfl_xor_sync(0xffffffffu, s0, off);
        s1 += __shfl_xor_sync(0xffffffffu, s1, off);
        s2 += __shfl_xor_sync(0xffffffffu, s2, off);
        s3 += __shfl_xor_sync(0xffffffffu, s3, off);
    }
    bool valid = (cnt >= 2);
    float r0 = 1.f/s0, r1 = 1.f/s1, r2 = 1.f/s2, r3 = 1.f/s3;
    for (int t = lane; t < cnt; t += 32){
        int col = g_ecols[s+t];
        float a = 0.f;
        if (valid){
            float4 l = NL[col];
            a = 0.25f*(expf(l.x - m0)*r0 + expf(l.y - m1)*r1 +
                       expf(l.z - m2)*r2 + expf(l.w - m3)*r3);
        }
        g_attn_np[g_enpos[s+t]] = a;
        atomicAdd(&g_nattn[col], a);
    }
}

// ================= K6: fused GEMM+LN (b<128) || AW row writer ======================
__global__ __launch_bounds__(256) void k6(const float* __restrict__ x,
                                          const float* __restrict__ out_w,
                                          const float* __restrict__ out_b,
                                          float* __restrict__ out,
                                          float* __restrict__ AW){
    extern __shared__ float smf[];
    int tid = threadIdx.x;

    if (blockIdx.x < GEMM_BLOCKS){
        float (*As)[MT+1]     = (float(*)[MT+1])smf;                    // 16 x 65
        float (*Bs)[HIDDEN+1] = (float(*)[HIDDEN+1])(smf + KT*(MT+1));  // 16 x 257
        float* Ss             = smf + KT*(MT+1) + KT*(HIDDEN+1);        // 64
        int tx = tid & 15;
        int ty = tid >> 4;
        int row0 = blockIdx.x * MT;

        if (tid < MT){
            int rr = row0 + tid;
            float c = (float)g_ncount[rr];
            Ss[tid] = g_nattn[rr] / fmaxf(c, 1.0f);
        }
        __syncthreads();

        float acc[4][16];
        #pragma unroll
        for (int i = 0; i < 4; i++)
            #pragma unroll
            for (int j = 0; j < 16; j++) acc[i][j] = 0.f;

        for (int k0 = 0; k0 < HIDDEN; k0 += KT){
            #pragma unroll
            for (int r = 0; r < 4; r++){                 // A: 64x16
                int q = tid + 256*r;
                int m = q >> 4, k = q & 15;
                As[k][m] = x[(long)(row0+m)*HIDDEN + k0 + k] * Ss[m];
            }
            #pragma unroll
            for (int r = 0; r < 16; r++){                // B: 256x16
                int q = tid + 256*r;
                int j = q >> 4, k = q & 15;
                Bs[k][j] = out_w[(long)j*HIDDEN + k0 + k];
            }
            __syncthreads();
            #pragma unroll
            for (int k = 0; k < KT; k++){
                float a[4], b[16];
                #pragma unroll
                for (int i = 0; i < 4; i++) a[i] = As[k][ty*4 + i];
                #pragma unroll
                for (int j = 0; j < 16; j++) b[j] = Bs[k][tx + 16*j];
                #pragma unroll
                for (int i = 0; i < 4; i++)
                    #pragma unroll
                    for (int j = 0; j < 16; j++) acc[i][j] += a[i]*b[j];
            }
            __syncthreads();
        }

        #pragma unroll
        for (int j = 0; j < 16; j++){
            float bb = out_b[tx + 16*j];
            #pragma unroll
            for (int i = 0; i < 4; i++) acc[i][j] += bb;
        }

        #pragma unroll
        for (int i = 0; i < 4; i++){
            float s = 0.f, s2 = 0.f;
            #pragma unroll
            for (int j = 0; j < 16; j++){ s += acc[i][j]; s2 += acc[i][j]*acc[i][j]; }
            #pragma unroll
            for (int off = 8; off; off >>= 1){
                s  += __shfl_xor_sync(0xffffffffu, s,  off);
                s2 += __shfl_xor_sync(0xffffffffu, s2, off);
            }
            float mu  = s * (1.f/256.f);
            float var = s2 * (1.f/256.f) - mu*mu;
            float inv = rsqrtf(var + 1e-5f);
            int row = row0 + ty*4 + i;
            float* op = out + (long)row*HIDDEN;
            #pragma unroll
            for (int j = 0; j < 16; j++)
                op[tx + 16*j] = (acc[i][j] - mu) * inv;
        }
    } else {
        // ---- one dense AW row per block ----
        __shared__ float sa[64];
        __shared__ int   ses[64];
        __shared__ int   sec[64];
        __shared__ int   sarr[64];
        float* srow = smf;                   // 8192 floats
        float4* srow4 = (float4*)srow;
        float4 z4 = make_float4(0.f,0.f,0.f,0.f);
        #pragma unroll
        for (int i = 0; i < 8; i++) srow4[tid + 256*i] = z4;
        __syncthreads();

        int n = blockIdx.x - GEMM_BLOCKS;
        int s = g_nstart[n], dcnt = g_ncount[n];

        for (int base = 0; base < dcnt; base += 64){
            int m = min(64, dcnt - base);
            // phase 1: coalesced incidence loads
            if (tid < m){
                float a = g_attn_np[s + base + tid];
                int e   = g_nedge[s + base + tid];
                int es  = g_estart[e];
                int ec  = (a != 0.f) ? g_ecount[e] : 0;
                sa[tid]  = a;
                ses[tid] = es;
                sec[tid] = ec;
                sarr[tid] = ec;
            }
            __syncthreads();
            // inclusive prefix over sarr[0..m)
            for (int off = 1; off < 64; off <<= 1){
                int v = 0;
                if (tid < m && tid >= off) v = sarr[tid - off];
                __syncthreads();
                if (tid < m && tid >= off) sarr[tid] += v;
                __syncthreads();
            }
            int T = sarr[m-1];
            // phase 2: flattened expansion
            for (int t = tid; t < T; t += 256){
                int lo = 0, hi = m-1;
                while (lo < hi){
                    int mid = (lo + hi) >> 1;
                    if (sarr[mid] > t) hi = mid; else lo = mid + 1;
                }
                int off = t - (sarr[lo] - sec[lo]);
                int col = g_ecols[ses[lo] + off];
                atomicAdd(&srow[col], sa[lo]);
            }
            __syncthreads();
        }
        if (tid == 0) srow[n] = 0.f;         // diagonal
        __syncthreads();
        float4* dst = (float4*)(AW + (long)n*N_NODES);
        #pragma unroll
        for (int i = 0; i < 8; i++)
            __stcs(dst + tid + 256*i, srow4[tid + 256*i]);
    }
}

// ---------------- launch ----------------
extern "C" void kernel_launch(void* const* d_in, const int* in_sizes, int n_in,
                              void* d_out, int out_size){
    const float* x        = (const float*)d_in[0];
    const int*   node_idx = (const int*)  d_in[1];
    const int*   edge_idx = (const int*)  d_in[2];
    const float* W_w      = (const float*)d_in[3];
    const float* W_b      = (const float*)d_in[4];
    const float* att      = (const float*)d_in[5];
    const float* out_w    = (const float*)d_in[6];
    const float* out_b    = (const float*)d_in[7];
    float* out = (float*)d_out;
    float* AW  = out + OUT_ELEMS;

    const int smem6 = 8192 * sizeof(float); // 32768 (>= GEMM's 20864)
    k1<<<33, 256>>>(W_w, W_b, att);
    k2<<<320, 256>>>(x, node_idx, edge_idx);
    k3<<<2, 1024>>>();
    k4<<<NUM_INC/256, 256>>>(node_idx, edge_idx);
    k5<<<NUM_EDGES/8, 256>>>();
    k6<<<GEMM_BLOCKS + N_NODES, 256, smem6>>>(x, out_w, out_b, out, AW);
}